// round 5
// baseline (speedup 1.0000x reference)
#include <cuda_runtime.h>

#define FULL 0xffffffffu

// theta-derived tables (sample-independent). Index I: bit q = qubit q.
// Layout in qsim: I = (g<<5)|j, g = lane&7 (qubits 5..7), j = reg idx (qubits 0..4).
__device__ float2 g_ry[16];
__device__ __align__(16) float2 g_d0[256];
__device__ __align__(16) float2 g_d1[256];

__global__ void precompute_kernel(const float* __restrict__ theta) {
    int I = threadIdx.x;          // 0..255
    if (I < 16) {
        int layer = I >> 3, q = I & 7;
        float th = theta[layer * 24 + q * 3 + 1];
        float s, c;
        sincosf(0.5f * th, &s, &c);
        g_ry[I] = make_float2(c, s);
    }
    // D0: RZ(phi) layer 0: bit=0 -> e^{-i phi/2}, bit=1 -> e^{+i phi/2}
    float a0 = 0.0f;
    #pragma unroll
    for (int q = 0; q < 8; q++) {
        float phi = theta[q * 3 + 0];
        a0 += ((I >> q) & 1) ? 0.5f * phi : -0.5f * phi;
    }
    float sr, cr;
    sincosf(a0, &sr, &cr);
    g_d0[I] = make_float2(cr, sr);

    // D1(K) = e^{i Om0(src(K))} * e^{i Phi1(K)}, src(K) = K ^ ((K & 0x7F) << 1)
    int src = I ^ ((I & 0x7F) << 1);
    float a1 = 0.0f;
    #pragma unroll
    for (int q = 0; q < 8; q++) {
        float om0  = theta[q * 3 + 2];
        float phi1 = theta[24 + q * 3 + 0];
        a1 += ((src >> q) & 1) ? 0.5f * om0  : -0.5f * om0;
        a1 += ((I   >> q) & 1) ? 0.5f * phi1 : -0.5f * phi1;
    }
    sincosf(a1, &sr, &cr);
    g_d1[I] = make_float2(cr, sr);
    // RZ(om) of layer 1 dropped: no effect on probabilities.
}

// In-place CNOT permutation step fused with D1 diagonal:
// new[DST] = D1[DST] * old[SRC]@srclane.  (DST/SRC are literal constants.)
#define PERM_STEP(DST, SRC) { \
    int sl_ = slA ^ (((DST) >> 4) & 1); \
    float pr_ = __shfl_sync(FULL, ar[SRC], sl_); \
    float pi_ = __shfl_sync(FULL, ai[SRC], sl_); \
    float2 d_ = d1f2[DST]; \
    ar[DST] = d_.x * pr_ - d_.y * pi_; \
    ai[DST] = d_.x * pi_ + d_.y * pr_; }

#define PERM_LAST(DST) { \
    int sl_ = slA ^ (((DST) >> 4) & 1); \
    float pr_ = __shfl_sync(FULL, tr_, sl_); \
    float pi_ = __shfl_sync(FULL, ti_, sl_); \
    float2 d_ = d1f2[DST]; \
    ar[DST] = d_.x * pr_ - d_.y * pi_; \
    ai[DST] = d_.x * pi_ + d_.y * pr_; }

__global__ void __launch_bounds__(128, 3)
qsim_kernel(const float* __restrict__ x, float* __restrict__ out, int batch) {
    int gw   = (int)((blockIdx.x * blockDim.x + threadIdx.x) >> 5);
    int lane = threadIdx.x & 31;
    int g    = lane & 7;        // qubits 5..7 (lane bits within 8-lane group)
    int base = lane & 24;       // group base lane
    int sample = gw * 4 + (lane >> 3);
    if (gw * 4 >= batch) return;
    int sidx = sample < batch ? sample : batch - 1;

    // ---- angle encoding: each lane computes qubit g's (cos,sin) ----
    float xv = x[sidx * 8 + g];
    xv = fminf(1.0f, fmaxf(-1.0f, xv));
    float sv, cv;
    sincospif(0.5f * xv, &sv, &cv);

    float cq[8], sq[8];
    #pragma unroll
    for (int q = 0; q < 8; q++) {
        cq[q] = __shfl_sync(FULL, cv, base | q);
        sq[q] = __shfl_sync(FULL, sv, base | q);
    }
    // lane factor over qubits 5,6,7 (g bits 0..2)
    float lf = ((g & 1) ? sq[5] : cq[5]) * ((g & 2) ? sq[6] : cq[6])
             * ((g & 4) ? sq[7] : cq[7]);

    // product over register qubits 0..4, lf folded at first level
    float a0v = lf * cq[0], a1v = lf * sq[0];
    float t2[4], t3[8], t4e[16], amp[32];
    #pragma unroll
    for (int j = 0; j < 4; j++)
        t2[j] = ((j & 1) ? a1v : a0v) * ((j & 2) ? sq[1] : cq[1]);
    #pragma unroll
    for (int j = 0; j < 8; j++)
        t3[j] = t2[j & 3] * ((j & 4) ? sq[2] : cq[2]);
    #pragma unroll
    for (int j = 0; j < 16; j++)
        t4e[j] = t3[j & 7] * ((j & 8) ? sq[3] : cq[3]);
    #pragma unroll
    for (int j = 0; j < 32; j++)
        amp[j] = t4e[j & 15] * ((j & 16) ? sq[4] : cq[4]);

    // apply D0 (phi-diagonal of layer 0)
    const float4* d0v = reinterpret_cast<const float4*>(g_d0) + g * 16;
    float ar[32], ai[32];
    #pragma unroll
    for (int jj = 0; jj < 16; jj++) {
        float4 d = d0v[jj];
        int j0 = 2 * jj, j1 = j0 + 1;
        ar[j0] = amp[j0] * d.x; ai[j0] = amp[j0] * d.y;
        ar[j1] = amp[j1] * d.z; ai[j1] = amp[j1] * d.w;
    }

    const int sg  = g ^ ((g & 3) << 1);  // CNOT perm: src lane bits (before j4 xor)
    const int slA = base | sg;
    const float2* d1f2 = reinterpret_cast<const float2*>(g_d1) + g * 32;

    // ---- two layers of real RY gates + merged diagonals ----
    #pragma unroll
    for (int layer = 0; layer < 2; layer++) {
        #pragma unroll
        for (int q = 0; q < 8; q++) {
            float2 gg = g_ry[layer * 8 + q];
            float cg = gg.x, sgv = gg.y;
            if (q < 5) {
                int m = 1 << q;
                #pragma unroll
                for (int j0 = 0; j0 < 32; j0++) {
                    if (j0 & m) continue;
                    int j1 = j0 | m;
                    float b0r = ar[j0], b0i = ai[j0];
                    float b1r = ar[j1], b1i = ai[j1];
                    ar[j0] = cg * b0r - sgv * b1r;
                    ai[j0] = cg * b0i - sgv * b1i;
                    ar[j1] = sgv * b0r + cg * b1r;
                    ai[j1] = sgv * b0i + cg * b1i;
                }
            } else {
                int pb = 1 << (q - 5);
                float ss = (g & pb) ? sgv : -sgv;
                #pragma unroll
                for (int j = 0; j < 32; j++) {
                    float pr = __shfl_xor_sync(FULL, ar[j], pb);
                    float pi = __shfl_xor_sync(FULL, ai[j], pb);
                    ar[j] = fmaf(ss, pr, cg * ar[j]);
                    ai[j] = fmaf(ss, pi, cg * ai[j]);
                }
            }
        }

        if (layer == 0) {
            // CNOT chain: new[I]=old[src(I)], src=I^((I&0x7F)<<1).
            // reg part sigma(j)=j^((j&15)<<1); lane part slA ^ (j>>4).
            // In-place along cycles of sigma, fused with D1.
            PERM_STEP(0, 0)
            PERM_STEP(16, 16)
            { float tr_ = ar[8], ti_ = ai[8];
              PERM_STEP(8, 24) PERM_LAST(24) }
            { float tr_ = ar[2], ti_ = ai[2];
              PERM_STEP(2, 6) PERM_STEP(6, 10) PERM_STEP(10, 30) PERM_LAST(30) }
            { float tr_ = ar[4], ti_ = ai[4];
              PERM_STEP(4, 12) PERM_STEP(12, 20) PERM_STEP(20, 28) PERM_LAST(28) }
            { float tr_ = ar[14], ti_ = ai[14];
              PERM_STEP(14, 18) PERM_STEP(18, 22) PERM_STEP(22, 26) PERM_LAST(26) }
            { float tr_ = ar[1], ti_ = ai[1];
              PERM_STEP(1, 3) PERM_STEP(3, 5) PERM_STEP(5, 15) PERM_STEP(15, 17)
              PERM_STEP(17, 19) PERM_STEP(19, 21) PERM_STEP(21, 31) PERM_LAST(31) }
            { float tr_ = ar[7], ti_ = ai[7];
              PERM_STEP(7, 9) PERM_STEP(9, 27) PERM_STEP(27, 13) PERM_STEP(13, 23)
              PERM_STEP(23, 25) PERM_STEP(25, 11) PERM_STEP(11, 29) PERM_LAST(29) }
        }
        // layer 1: om-diag dropped; its CNOT chain folded into Walsh below.
    }

    // ---- measurement: e_q = sum_I (-1)^{parity(I & (2^{q+1}-1))} p_I ----
    float p[32];
    #pragma unroll
    for (int j = 0; j < 32; j++)
        p[j] = ar[j] * ar[j] + ai[j] * ai[j];

    // signed prefix-parity cascade over reg bits 0..4
    float c1[16], c2[8], c3[4], c4[2];
    #pragma unroll
    for (int k = 0; k < 16; k++) c1[k] = p[2 * k] - p[2 * k + 1];
    #pragma unroll
    for (int k = 0; k < 8; k++)  c2[k] = c1[2 * k] - c1[2 * k + 1];
    #pragma unroll
    for (int k = 0; k < 4; k++)  c3[k] = c2[2 * k] - c2[2 * k + 1];
    c4[0] = c3[0] - c3[1]; c4[1] = c3[2] - c3[3];
    float t0 = 0.0f, t1 = 0.0f, t2s = 0.0f;
    #pragma unroll
    for (int k = 0; k < 16; k++) t0 += c1[k];
    #pragma unroll
    for (int k = 0; k < 8; k++)  t1 += c2[k];
    #pragma unroll
    for (int k = 0; k < 4; k++)  t2s += c3[k];
    float t3s = c4[0] + c4[1];
    float t4s = c4[0] - c4[1];

    // group reductions over 8 lanes: plain sums for t0..t3, Walsh for t4
    #pragma unroll
    for (int d = 1; d < 8; d <<= 1) {
        t0  += __shfl_xor_sync(FULL, t0, d);
        t1  += __shfl_xor_sync(FULL, t1, d);
        t2s += __shfl_xor_sync(FULL, t2s, d);
        t3s += __shfl_xor_sync(FULL, t3s, d);
        float pv = __shfl_xor_sync(FULL, t4s, d);
        t4s = (g & d) ? (pv - t4s) : (t4s + pv);
    }

    if (sample < batch) {
        float* o = out + sample * 8;
        if (g == 0) { o[0] = t0; o[1] = t1; o[2] = t2s; o[3] = t3s; }
        if ((g & (g + 1)) == 0)       // g = 0,1,3,7 -> qubits 4,5,6,7
            o[4 + __popc(g)] = t4s;
    }
}

extern "C" void kernel_launch(void* const* d_in, const int* in_sizes, int n_in,
                              void* d_out, int out_size) {
    const float* inputs = (const float*)d_in[0];   // [16384, 8] f32
    const float* theta  = (const float*)d_in[1];   // [2, 8, 3]  f32
    float* out = (float*)d_out;                    // [16384, 8] f32

    int batch = in_sizes[0] / 8;

    precompute_kernel<<<1, 256>>>(theta);

    int warps = (batch + 3) / 4;             // 4 samples per warp
    int threads = 128;                       // 4 warps / block
    int blocks = (warps * 32 + threads - 1) / threads;
    qsim_kernel<<<blocks, threads>>>(inputs, out, batch);
}